// round 14
// baseline (speedup 1.0000x reference)
#include <cuda_runtime.h>
#include <cstdint>

// x [4,512,128] f32, y [512,128] f32 -> out [4,512,512,3] f32 (cos, L1, L2)
// L1 via SIMT packed-f32 (2 fma-ops/elem); dot via bf16-split tensor MMA;
// cos = dot*rx*ry, p2 = sqrt(xsq+ysq-2dot).
#define R_TOTAL 2048
#define C_TOTAL 512
#define D_DIM   128
#define NDD2    64

#define BM 128
#define BN 64
#define XTS 129                 // xsT stride per dd2 (u64)
#define YTS 66                  // ysT stride per dd2 (u64)
#define BTS 66                  // bf16 hi/lo tile row stride (u32)

// smem layout (bytes)
#define XS_OFF   0
#define YS_OFF   (XS_OFF + NDD2 * XTS * 8)            // 66048
#define XHI_OFF  (YS_OFF + NDD2 * YTS * 8)            // 99840
#define XLO_OFF  (XHI_OFF + BM * BTS * 4)             // 133632
#define YHI_OFF  (XLO_OFF + BM * BTS * 4)             // 167424
#define YLO_OFF  (YHI_OFF + BN * BTS * 4)             // 184320
#define NSQ_OFF  (YLO_OFF + BN * BTS * 4)             // 201216
#define NRN_OFF  (NSQ_OFF + 192 * 4)
#define SMEM_BYTES (NRN_OFF + 192 * 4)                // 202752

typedef unsigned long long u64;
typedef unsigned int u32;
struct __align__(16) ull2 { u64 x, y; };

__device__ __forceinline__ u64 ffma2(u64 a, u64 b, u64 c) {
    u64 d; asm("fma.rn.f32x2 %0, %1, %2, %3;" : "=l"(d) : "l"(a), "l"(b), "l"(c));
    return d;
}
__device__ __forceinline__ u64 fadd2(u64 a, u64 b) {
    u64 d; asm("add.rn.f32x2 %0, %1, %2;" : "=l"(d) : "l"(a), "l"(b));
    return d;
}
__device__ __forceinline__ float f2lo(u64 d) { return __uint_as_float((u32)(d & 0xFFFFFFFFu)); }
__device__ __forceinline__ float f2hi(u64 d) { return __uint_as_float((u32)(d >> 32)); }
__device__ __forceinline__ u64 pack2(float lo, float hi) {
    return ((u64)__float_as_uint(hi) << 32) | (u64)__float_as_uint(lo);
}
// d[15:0] = bf16(lo_elem), d[31:16] = bf16(hi_elem)
__device__ __forceinline__ u32 bfpack(float lo_elem, float hi_elem) {
    u32 r; asm("cvt.rn.bf16x2.f32 %0, %1, %2;" : "=r"(r) : "f"(hi_elem), "f"(lo_elem));
    return r;
}
__device__ __forceinline__ float bflo_f(u32 p) { return __uint_as_float(p << 16); }
__device__ __forceinline__ float bfhi_f(u32 p) { return __uint_as_float(p & 0xFFFF0000u); }

__device__ __forceinline__ void mma_bf16(float (&c)[4], u32 a0, u32 a1, u32 a2, u32 a3,
                                         u32 b0, u32 b1) {
    asm("mma.sync.aligned.m16n8k16.row.col.f32.bf16.bf16.f32 "
        "{%0,%1,%2,%3}, {%4,%5,%6,%7}, {%8,%9}, {%0,%1,%2,%3};"
        : "+f"(c[0]), "+f"(c[1]), "+f"(c[2]), "+f"(c[3])
        : "r"(a0), "r"(a1), "r"(a2), "r"(a3), "r"(b0), "r"(b1));
}

__global__ void __launch_bounds__(512, 1)
dist_kernel(const float* __restrict__ x, const float* __restrict__ y,
            float* __restrict__ out) {
    extern __shared__ __align__(16) char smem[];
    u64* xsT = reinterpret_cast<u64*>(smem + XS_OFF);   // [NDD2][XTS] f32 packed
    u64* ysT = reinterpret_cast<u64*>(smem + YS_OFF);   // [NDD2][YTS] (-y) packed
    u32* xhi = reinterpret_cast<u32*>(smem + XHI_OFF);  // [BM][BTS] bf16-pair hi
    u32* xlo = reinterpret_cast<u32*>(smem + XLO_OFF);
    u32* yhi = reinterpret_cast<u32*>(smem + YHI_OFF);  // [BN][BTS] (+y)
    u32* ylo = reinterpret_cast<u32*>(smem + YLO_OFF);
    float* nsq = reinterpret_cast<float*>(smem + NSQ_OFF); // [192]: 128 x + 64 y
    float* nrn = reinterpret_cast<float*>(smem + NRN_OFF);

    const int R0 = blockIdx.x * BM;     // grid.x = 16
    const int C0 = blockIdx.y * BN;     // grid.y = 8
    const int t  = threadIdx.x;
    const int tx = t & 31;
    const int ty = t >> 5;

    // ---- stage x: f32 transposed + bf16 hi/lo row-major
    #pragma unroll
    for (int s = 0; s < 8; s++) {
        int idx  = t + 512 * s;         // 0..4095
        int row  = idx >> 5;            // 0..127
        int col4 = idx & 31;
        float4 v = *reinterpret_cast<const float4*>(
            x + (size_t)(R0 + row) * D_DIM + col4 * 4);
        xsT[(2 * col4) * XTS + row]     = pack2(v.x, v.y);
        xsT[(2 * col4 + 1) * XTS + row] = pack2(v.z, v.w);
        u32 h0 = bfpack(v.x, v.y);
        u32 h1 = bfpack(v.z, v.w);
        u32 l0 = bfpack(v.x - bflo_f(h0), v.y - bfhi_f(h0));
        u32 l1 = bfpack(v.z - bflo_f(h1), v.w - bfhi_f(h1));
        xhi[row * BTS + 2 * col4]     = h0;
        xhi[row * BTS + 2 * col4 + 1] = h1;
        xlo[row * BTS + 2 * col4]     = l0;
        xlo[row * BTS + 2 * col4 + 1] = l1;
    }
    // ---- stage y: negated f32 transposed + positive bf16 hi/lo
    #pragma unroll
    for (int s = 0; s < 4; s++) {
        int idx  = t + 512 * s;         // 0..2047
        int row  = idx >> 5;            // 0..63
        int col4 = idx & 31;
        float4 v = *reinterpret_cast<const float4*>(
            y + (size_t)(C0 + row) * D_DIM + col4 * 4);
        ysT[(2 * col4) * YTS + row]     = pack2(-v.x, -v.y);
        ysT[(2 * col4 + 1) * YTS + row] = pack2(-v.z, -v.w);
        u32 h0 = bfpack(v.x, v.y);
        u32 h1 = bfpack(v.z, v.w);
        u32 l0 = bfpack(v.x - bflo_f(h0), v.y - bfhi_f(h0));
        u32 l1 = bfpack(v.z - bflo_f(h1), v.w - bfhi_f(h1));
        yhi[row * BTS + 2 * col4]     = h0;
        yhi[row * BTS + 2 * col4 + 1] = h1;
        ylo[row * BTS + 2 * col4]     = l0;
        ylo[row * BTS + 2 * col4 + 1] = l1;
    }
    __syncthreads();

    // ---- fused norms: t<128 -> x row t; 128<=t<192 -> y row t-128 ((-y)^2==y^2)
    if (t < 192) {
        const u64* base; int stride;
        if (t < 128) { base = xsT + t;         stride = XTS; }
        else         { base = ysT + (t - 128); stride = YTS; }
        u64 a = 0ULL;
        #pragma unroll 8
        for (int dd2 = 0; dd2 < NDD2; dd2++) {
            u64 v = base[dd2 * stride];
            a = ffma2(v, v, a);
        }
        float s = f2lo(a) + f2hi(a);
        nsq[t] = s;
        nrn[t] = rsqrtf(s);
    }
    __syncthreads();

    // ================= tensor phase: dot via bf16-split MMA =================
    {
        const int w    = t >> 5;
        const int lane = t & 31;
        const int gid  = lane >> 2;     // 0..7
        const int tig  = lane & 3;      // 0..3
        const int m0   = (w >> 1) * 16; // 8 m-tiles of 16 rows
        const int nh   = (w & 1) * 32;  // n half

        float c[4][4];
        #pragma unroll
        for (int nt = 0; nt < 4; nt++)
            #pragma unroll
            for (int q = 0; q < 4; q++) c[nt][q] = 0.0f;

        #pragma unroll
        for (int step = 0; step < 8; step++) {
            int kc = step * 8;          // u32-pair units (16 d per step)
            int ra = (m0 + gid) * BTS + tig + kc;
            int rb = ra + 8 * BTS;
            u32 ah0 = xhi[ra], ah1 = xhi[rb], ah2 = xhi[ra + 4], ah3 = xhi[rb + 4];
            u32 al0 = xlo[ra], al1 = xlo[rb], al2 = xlo[ra + 4], al3 = xlo[rb + 4];
            #pragma unroll
            for (int nt = 0; nt < 4; nt++) {
                int rn = (nh + nt * 8 + gid) * BTS + tig + kc;
                u32 bh0 = yhi[rn], bh1 = yhi[rn + 4];
                u32 bl0 = ylo[rn], bl1 = ylo[rn + 4];
                mma_bf16(c[nt], ah0, ah1, ah2, ah3, bh0, bh1);   // hi*hi
                mma_bf16(c[nt], ah0, ah1, ah2, ah3, bl0, bl1);   // hi*lo
                mma_bf16(c[nt], al0, al1, al2, al3, bh0, bh1);   // lo*hi
            }
        }

        // MMA epilogue: cos + p2 (fields 0 and 2)
        #pragma unroll
        for (int nt = 0; nt < 4; nt++) {
            #pragma unroll
            for (int q = 0; q < 4; q++) {
                int lr = m0 + gid + (q >> 1) * 8;          // local x row
                int lc = nh + nt * 8 + 2 * tig + (q & 1);  // local y col
                float dot = c[nt][q];
                float s2  = fmaxf(nsq[lr] + nsq[128 + lc] - 2.0f * dot, 0.0f);
                float p2  = sqrtf(s2);
                float cosv = dot * nrn[lr] * nrn[128 + lc];
                size_t idx = ((size_t)(R0 + lr) * C_TOTAL + (C0 + lc)) * 3;
                out[idx + 0] = cosv;
                out[idx + 2] = p2;
            }
        }
    }

    // ================= SIMT phase: L1 only (2 packed ops/elem-pair) =========
    const u64 ABSM = 0x7FFFFFFF7FFFFFFFULL;

    u64 acc1[8][2];
    #pragma unroll
    for (int i = 0; i < 8; i++) { acc1[i][0] = 0ULL; acc1[i][1] = 0ULL; }

    const u64*  px = xsT + ty;                                    // x rows ty+16i
    const ull2* py = reinterpret_cast<const ull2*>(ysT + 2 * tx); // y cols 2tx,2tx+1

    #pragma unroll 4
    for (int dd2 = 0; dd2 < NDD2; dd2++) {
        u64 xv[8];
        #pragma unroll
        for (int i = 0; i < 8; i++) xv[i] = px[16 * i];   // broadcast LDS.64
        ull2 yv = *py;                                    // LDS.128

        #pragma unroll
        for (int i = 0; i < 8; i++) {
            u64 e0 = fadd2(xv[i], yv.x);
            u64 e1 = fadd2(xv[i], yv.y);
            acc1[i][0] = fadd2(acc1[i][0], e0 & ABSM);
            acc1[i][1] = fadd2(acc1[i][1], e1 & ABSM);
        }

        px += XTS;
        py += YTS / 2;
    }

    // L1 epilogue (field 1)
    #pragma unroll
    for (int i = 0; i < 8; i++) {
        int gr = R0 + ty + 16 * i;
        #pragma unroll
        for (int j = 0; j < 2; j++) {
            int gc = C0 + 2 * tx + j;
            float s1 = f2lo(acc1[i][j]) + f2hi(acc1[i][j]);
            out[((size_t)gr * C_TOTAL + gc) * 3 + 1] = s1;
        }
    }
}

extern "C" void kernel_launch(void* const* d_in, const int* in_sizes, int n_in,
                              void* d_out, int out_size) {
    const float* x = (const float*)d_in[0];
    const float* y = (const float*)d_in[1];
    float* out = (float*)d_out;

    static int attr_done = 0;
    if (!attr_done) {
        cudaFuncSetAttribute(dist_kernel,
                             cudaFuncAttributeMaxDynamicSharedMemorySize, SMEM_BYTES);
        cudaFuncSetAttribute(dist_kernel,
                             cudaFuncAttributePreferredSharedMemoryCarveout, 100);
        attr_done = 1;
    }

    dim3 grid(R_TOTAL / BM, C_TOTAL / BN);   // 16 x 8 = 128 blocks, 1 CTA/SM, one wave
    dist_kernel<<<grid, 512, SMEM_BYTES>>>(x, y, out);
}

// round 15
// speedup vs baseline: 1.2162x; 1.2162x over previous
#include <cuda_runtime.h>
#include <cstdint>

// x [4,512,128] f32, y [512,128] f32 -> out [4,512,512,3] f32 (cos, L1, L2)
// L1 via SIMT packed-f32; dot via bf16-split tensor MMA (hi*hi+hi*lo+lo*hi);
// cos = dot*rx*ry, p2 = sqrt(xsq+ysq-2dot). Dot staged through smem so the
// final store pass writes all 3 fields contiguously.
#define R_TOTAL 2048
#define C_TOTAL 512
#define D_DIM   128
#define NDD2    64

#define BM 128
#define BN 64
#define XTS 129                 // f32-pair x tile stride per dd2 (u64)
#define YTS 66                  // f32-pair y tile stride per dd2 (u64)
#define BTS 68                  // bf16-pair tile row stride (u32); 272B -> LDSM conflict-free
#define DTS 66                  // dot matrix row stride (f32)

// smem layout (bytes)
#define XS_OFF   0
#define YS_OFF   (XS_OFF + NDD2 * XTS * 8)            // 66048
#define XHI_OFF  (YS_OFF + NDD2 * YTS * 8)            // 99840  (reused as dot matrix)
#define XLO_OFF  (XHI_OFF + BM * BTS * 4)             // 134656
#define YHI_OFF  (XLO_OFF + BM * BTS * 4)             // 169472
#define YLO_OFF  (YHI_OFF + BN * BTS * 4)             // 186880
#define NSQ_OFF  (YLO_OFF + BN * BTS * 4)             // 204288
#define NRN_OFF  (NSQ_OFF + 192 * 4)
#define SMEM_BYTES (NRN_OFF + 192 * 4)                // 205824

typedef unsigned long long u64;
typedef unsigned int u32;
struct __align__(16) ull2 { u64 x, y; };

__device__ __forceinline__ u64 ffma2(u64 a, u64 b, u64 c) {
    u64 d; asm("fma.rn.f32x2 %0, %1, %2, %3;" : "=l"(d) : "l"(a), "l"(b), "l"(c));
    return d;
}
__device__ __forceinline__ u64 fadd2(u64 a, u64 b) {
    u64 d; asm("add.rn.f32x2 %0, %1, %2;" : "=l"(d) : "l"(a), "l"(b));
    return d;
}
__device__ __forceinline__ float f2lo(u64 d) { return __uint_as_float((u32)(d & 0xFFFFFFFFu)); }
__device__ __forceinline__ float f2hi(u64 d) { return __uint_as_float((u32)(d >> 32)); }
__device__ __forceinline__ u64 pack2(float lo, float hi) {
    return ((u64)__float_as_uint(hi) << 32) | (u64)__float_as_uint(lo);
}
// d[15:0] = bf16(lo_elem), d[31:16] = bf16(hi_elem)
__device__ __forceinline__ u32 bfpack(float lo_elem, float hi_elem) {
    u32 r; asm("cvt.rn.bf16x2.f32 %0, %1, %2;" : "=r"(r) : "f"(hi_elem), "f"(lo_elem));
    return r;
}
__device__ __forceinline__ float bflo_f(u32 p) { return __uint_as_float(p << 16); }
__device__ __forceinline__ float bfhi_f(u32 p) { return __uint_as_float(p & 0xFFFF0000u); }

__device__ __forceinline__ void mma_bf16(float (&c)[4], const u32* a, u32 b0, u32 b1) {
    asm("mma.sync.aligned.m16n8k16.row.col.f32.bf16.bf16.f32 "
        "{%0,%1,%2,%3}, {%4,%5,%6,%7}, {%8,%9}, {%0,%1,%2,%3};"
        : "+f"(c[0]), "+f"(c[1]), "+f"(c[2]), "+f"(c[3])
        : "r"(a[0]), "r"(a[1]), "r"(a[2]), "r"(a[3]), "r"(b0), "r"(b1));
}
__device__ __forceinline__ void ldsm_x4(u32* r, u32 addr) {
    asm volatile("ldmatrix.sync.aligned.m8n8.x4.shared.b16 {%0,%1,%2,%3}, [%4];"
        : "=r"(r[0]), "=r"(r[1]), "=r"(r[2]), "=r"(r[3]) : "r"(addr));
}

__global__ void __launch_bounds__(512, 1)
dist_kernel(const float* __restrict__ x, const float* __restrict__ y,
            float* __restrict__ out) {
    extern __shared__ __align__(16) char smem[];
    u64* xsT = reinterpret_cast<u64*>(smem + XS_OFF);   // [NDD2][XTS] f32 packed
    u64* ysT = reinterpret_cast<u64*>(smem + YS_OFF);   // [NDD2][YTS] (-y) packed
    u32* xhi = reinterpret_cast<u32*>(smem + XHI_OFF);  // [BM][BTS] bf16-pair hi
    u32* xlo = reinterpret_cast<u32*>(smem + XLO_OFF);
    u32* yhi = reinterpret_cast<u32*>(smem + YHI_OFF);  // [BN][BTS] (+y)
    u32* ylo = reinterpret_cast<u32*>(smem + YLO_OFF);
    float* nsq = reinterpret_cast<float*>(smem + NSQ_OFF); // [192]: 128 x + 64 y
    float* nrn = reinterpret_cast<float*>(smem + NRN_OFF);
    float* dotm = reinterpret_cast<float*>(smem + XHI_OFF); // reuses xhi after MMA

    const int R0 = blockIdx.x * BM;     // grid.x = 16
    const int C0 = blockIdx.y * BN;     // grid.y = 8
    const int t  = threadIdx.x;
    const int tx = t & 31;
    const int ty = t >> 5;

    // ---- stage x: f32 transposed + bf16 hi/lo row-major
    #pragma unroll
    for (int s = 0; s < 8; s++) {
        int idx  = t + 512 * s;         // 0..4095
        int row  = idx >> 5;            // 0..127
        int col4 = idx & 31;
        float4 v = *reinterpret_cast<const float4*>(
            x + (size_t)(R0 + row) * D_DIM + col4 * 4);
        xsT[(2 * col4) * XTS + row]     = pack2(v.x, v.y);
        xsT[(2 * col4 + 1) * XTS + row] = pack2(v.z, v.w);
        u32 h0 = bfpack(v.x, v.y);
        u32 h1 = bfpack(v.z, v.w);
        u32 l0 = bfpack(v.x - bflo_f(h0), v.y - bfhi_f(h0));
        u32 l1 = bfpack(v.z - bflo_f(h1), v.w - bfhi_f(h1));
        xhi[row * BTS + 2 * col4]     = h0;
        xhi[row * BTS + 2 * col4 + 1] = h1;
        xlo[row * BTS + 2 * col4]     = l0;
        xlo[row * BTS + 2 * col4 + 1] = l1;
    }
    // ---- stage y: negated f32 transposed + positive bf16 hi/lo
    #pragma unroll
    for (int s = 0; s < 4; s++) {
        int idx  = t + 512 * s;         // 0..2047
        int row  = idx >> 5;            // 0..63
        int col4 = idx & 31;
        float4 v = *reinterpret_cast<const float4*>(
            y + (size_t)(C0 + row) * D_DIM + col4 * 4);
        ysT[(2 * col4) * YTS + row]     = pack2(-v.x, -v.y);
        ysT[(2 * col4 + 1) * YTS + row] = pack2(-v.z, -v.w);
        u32 h0 = bfpack(v.x, v.y);
        u32 h1 = bfpack(v.z, v.w);
        u32 l0 = bfpack(v.x - bflo_f(h0), v.y - bfhi_f(h0));
        u32 l1 = bfpack(v.z - bflo_f(h1), v.w - bfhi_f(h1));
        yhi[row * BTS + 2 * col4]     = h0;
        yhi[row * BTS + 2 * col4 + 1] = h1;
        ylo[row * BTS + 2 * col4]     = l0;
        ylo[row * BTS + 2 * col4 + 1] = l1;
    }
    __syncthreads();

    // ---- fused norms: t<128 -> x row t; 128<=t<192 -> y row t-128
    if (t < 192) {
        const u64* base; int stride;
        if (t < 128) { base = xsT + t;         stride = XTS; }
        else         { base = ysT + (t - 128); stride = YTS; }
        u64 a = 0ULL;
        #pragma unroll 8
        for (int dd2 = 0; dd2 < NDD2; dd2++) {
            u64 v = base[dd2 * stride];
            a = ffma2(v, v, a);
        }
        float s = f2lo(a) + f2hi(a);
        nsq[t] = s;
        nrn[t] = rsqrtf(s);
    }
    __syncthreads();

    // ================= tensor phase: dot via bf16-split MMA + ldmatrix ======
    {
        const int w    = t >> 5;
        const int lane = t & 31;
        const int gid  = lane >> 2;     // 0..7
        const int tig  = lane & 3;      // 0..3
        const int m0   = (w >> 1) * 16; // 8 m-tiles of 16 rows
        const int nh   = (w & 1) * 32;  // n half

        // ldmatrix lane addresses (u32 words within tile, converted to bytes)
        // A .x4: tiles [m0-7,k0-7][m8-15,k0-7][m0-7,k8-15][m8-15,k8-15]
        const int arow = m0 + (lane & 15);
        const int acol = (lane >> 4) * 4;
        u32 xhi_sa = (u32)__cvta_generic_to_shared(xhi);
        u32 xlo_sa = (u32)__cvta_generic_to_shared(xlo);
        u32 yhi_sa = (u32)__cvta_generic_to_shared(yhi);
        u32 ylo_sa = (u32)__cvta_generic_to_shared(ylo);
        u32 aOff = (u32)(arow * BTS + acol) << 2;
        // B .x4 pair p covers n-tiles 2p,2p+1: tiles [n0-7,k0][n0-7,k8][n8-15,k0][n8-15,k8]
        const int brow = (lane & 7) + ((lane >> 4) & 1) * 8;
        const int bcol = ((lane >> 3) & 1) * 4;
        u32 bOff0 = (u32)((nh + brow) * BTS + bcol) << 2;
        u32 bOff1 = (u32)((nh + 16 + brow) * BTS + bcol) << 2;

        float c[4][4];
        #pragma unroll
        for (int nt = 0; nt < 4; nt++)
            #pragma unroll
            for (int q = 0; q < 4; q++) c[nt][q] = 0.0f;

        #pragma unroll
        for (int step = 0; step < 8; step++) {
            u32 kb = (u32)(step * 8) << 2;   // byte advance per step (8 u32)
            u32 ah[4], al[4], bh0[4], bh1[4], bl0[4], bl1[4];
            ldsm_x4(ah, xhi_sa + aOff + kb);
            ldsm_x4(al, xlo_sa + aOff + kb);
            ldsm_x4(bh0, yhi_sa + bOff0 + kb);   // b frags for nt0 (r0,r1), nt1 (r2,r3)
            ldsm_x4(bh1, yhi_sa + bOff1 + kb);   // nt2, nt3
            ldsm_x4(bl0, ylo_sa + bOff0 + kb);
            ldsm_x4(bl1, ylo_sa + bOff1 + kb);

            mma_bf16(c[0], ah, bh0[0], bh0[1]);
            mma_bf16(c[0], ah, bl0[0], bl0[1]);
            mma_bf16(c[0], al, bh0[0], bh0[1]);
            mma_bf16(c[1], ah, bh0[2], bh0[3]);
            mma_bf16(c[1], ah, bl0[2], bl0[3]);
            mma_bf16(c[1], al, bh0[2], bh0[3]);
            mma_bf16(c[2], ah, bh1[0], bh1[1]);
            mma_bf16(c[2], ah, bl1[0], bl1[1]);
            mma_bf16(c[2], al, bh1[0], bh1[1]);
            mma_bf16(c[3], ah, bh1[2], bh1[3]);
            mma_bf16(c[3], ah, bl1[2], bl1[3]);
            mma_bf16(c[3], al, bh1[2], bh1[3]);
        }

        __syncthreads();   // all warps done reading bf16 tiles

        // store dot fragments into smem (overwrites xhi region)
        // c[nt][q]: lr = m0+gid+(q>>1)*8, lc = nh+nt*8+2*tig+(q&1)
        #pragma unroll
        for (int nt = 0; nt < 4; nt++) {
            #pragma unroll
            for (int qh = 0; qh < 2; qh++) {
                int lr = m0 + gid + qh * 8;
                int lc = nh + nt * 8 + 2 * tig;
                *reinterpret_cast<float2*>(&dotm[lr * DTS + lc]) =
                    make_float2(c[nt][qh * 2], c[nt][qh * 2 + 1]);
            }
        }
    }
    __syncthreads();

    // ================= SIMT phase: L1 only =================================
    const u64 ABSM = 0x7FFFFFFF7FFFFFFFULL;

    u64 acc1[8][2];
    #pragma unroll
    for (int i = 0; i < 8; i++) { acc1[i][0] = 0ULL; acc1[i][1] = 0ULL; }

    const u64*  px = xsT + ty;                                    // x rows ty+16i
    const ull2* py = reinterpret_cast<const ull2*>(ysT + 2 * tx); // y cols 2tx,2tx+1

    #pragma unroll 4
    for (int dd2 = 0; dd2 < NDD2; dd2++) {
        u64 xv[8];
        #pragma unroll
        for (int i = 0; i < 8; i++) xv[i] = px[16 * i];   // broadcast LDS.64
        ull2 yv = *py;                                    // LDS.128

        #pragma unroll
        for (int i = 0; i < 8; i++) {
            u64 e0 = fadd2(xv[i], yv.x);
            u64 e1 = fadd2(xv[i], yv.y);
            acc1[i][0] = fadd2(acc1[i][0], e0 & ABSM);
            acc1[i][1] = fadd2(acc1[i][1], e1 & ABSM);
        }

        px += XTS;
        py += YTS / 2;
    }

    // ---- single coalesced epilogue: all 3 fields, 3x STG.64 per row ----
    #pragma unroll
    for (int i = 0; i < 8; i++) {
        int lrow = ty + 16 * i;
        int gr = R0 + lrow;
        float xsq = nsq[lrow];
        float xrn = nrn[lrow];
        float2 dv = *reinterpret_cast<const float2*>(&dotm[lrow * DTS + 2 * tx]);
        float o[6];
        #pragma unroll
        for (int j = 0; j < 2; j++) {
            int lcol = 2 * tx + j;
            float dot = (j == 0) ? dv.x : dv.y;
            float s1 = f2lo(acc1[i][j]) + f2hi(acc1[i][j]);
            float s2 = fmaxf(xsq + nsq[128 + lcol] - 2.0f * dot, 0.0f);
            float p2 = sqrtf(s2);
            float cosv = dot * xrn * nrn[128 + lcol];
            o[3 * j + 0] = cosv;
            o[3 * j + 1] = s1;
            o[3 * j + 2] = p2;
        }
        size_t base = ((size_t)gr * C_TOTAL + C0 + 2 * tx) * 3;
        float2* dst = reinterpret_cast<float2*>(out + base);
        dst[0] = make_float2(o[0], o[1]);
        dst[1] = make_float2(o[2], o[3]);
        dst[2] = make_float2(o[4], o[5]);
    }
}

extern "C" void kernel_launch(void* const* d_in, const int* in_sizes, int n_in,
                              void* d_out, int out_size) {
    const float* x = (const float*)d_in[0];
    const float* y = (const float*)d_in[1];
    float* out = (float*)d_out;

    static int attr_done = 0;
    if (!attr_done) {
        cudaFuncSetAttribute(dist_kernel,
                             cudaFuncAttributeMaxDynamicSharedMemorySize, SMEM_BYTES);
        cudaFuncSetAttribute(dist_kernel,
                             cudaFuncAttributePreferredSharedMemoryCarveout, 100);
        attr_done = 1;
    }

    dim3 grid(R_TOTAL / BM, C_TOTAL / BN);   // 16 x 8 = 128 blocks, 1 CTA/SM, one wave
    dist_kernel<<<grid, 512, SMEM_BYTES>>>(x, y, out);
}

// round 16
// speedup vs baseline: 1.3061x; 1.0740x over previous
#include <cuda_runtime.h>
#include <cstdint>

// x [4,512,128] f32, y [512,128] f32 -> out [4,512,512,3] f32 (cos, L1, L2)
// L1 via SIMT packed-f32; dot via bf16-split tensor MMA interleaved INTO the
// L1 loop (tensor + fma pipes overlap). cos = dot*rx*ry, p2 = sqrt(xsq+ysq-2dot).
#define R_TOTAL 2048
#define C_TOTAL 512
#define D_DIM   128
#define NDD2    64

#define BM 128
#define BN 64
#define XTS 129                 // f32-pair x tile stride per dd2 (u64)
#define YTS 66                  // f32-pair y tile stride per dd2 (u64)
#define BTS 68                  // bf16-pair tile row stride (u32); 272B -> LDSM conflict-free
#define DTS 66                  // dot matrix row stride (f32)

// smem layout (bytes)
#define XS_OFF   0
#define YS_OFF   (XS_OFF + NDD2 * XTS * 8)            // 66048
#define XHI_OFF  (YS_OFF + NDD2 * YTS * 8)            // 99840  (reused as dot matrix)
#define XLO_OFF  (XHI_OFF + BM * BTS * 4)             // 134656
#define YHI_OFF  (XLO_OFF + BM * BTS * 4)             // 169472
#define YLO_OFF  (YHI_OFF + BN * BTS * 4)             // 186880
#define NSQ_OFF  (YLO_OFF + BN * BTS * 4)             // 204288
#define NRN_OFF  (NSQ_OFF + 192 * 4)
#define SMEM_BYTES (NRN_OFF + 192 * 4)                // 205824

typedef unsigned long long u64;
typedef unsigned int u32;
struct __align__(16) ull2 { u64 x, y; };

__device__ __forceinline__ u64 ffma2(u64 a, u64 b, u64 c) {
    u64 d; asm("fma.rn.f32x2 %0, %1, %2, %3;" : "=l"(d) : "l"(a), "l"(b), "l"(c));
    return d;
}
__device__ __forceinline__ u64 fadd2(u64 a, u64 b) {
    u64 d; asm("add.rn.f32x2 %0, %1, %2;" : "=l"(d) : "l"(a), "l"(b));
    return d;
}
__device__ __forceinline__ float f2lo(u64 d) { return __uint_as_float((u32)(d & 0xFFFFFFFFu)); }
__device__ __forceinline__ float f2hi(u64 d) { return __uint_as_float((u32)(d >> 32)); }
__device__ __forceinline__ u64 pack2(float lo, float hi) {
    return ((u64)__float_as_uint(hi) << 32) | (u64)__float_as_uint(lo);
}
// d[15:0] = bf16(lo_elem), d[31:16] = bf16(hi_elem)
__device__ __forceinline__ u32 bfpack(float lo_elem, float hi_elem) {
    u32 r; asm("cvt.rn.bf16x2.f32 %0, %1, %2;" : "=r"(r) : "f"(hi_elem), "f"(lo_elem));
    return r;
}
__device__ __forceinline__ float bflo_f(u32 p) { return __uint_as_float(p << 16); }
__device__ __forceinline__ float bfhi_f(u32 p) { return __uint_as_float(p & 0xFFFF0000u); }

__device__ __forceinline__ void mma_bf16(float (&c)[4], const u32* a, u32 b0, u32 b1) {
    asm("mma.sync.aligned.m16n8k16.row.col.f32.bf16.bf16.f32 "
        "{%0,%1,%2,%3}, {%4,%5,%6,%7}, {%8,%9}, {%0,%1,%2,%3};"
        : "+f"(c[0]), "+f"(c[1]), "+f"(c[2]), "+f"(c[3])
        : "r"(a[0]), "r"(a[1]), "r"(a[2]), "r"(a[3]), "r"(b0), "r"(b1));
}
__device__ __forceinline__ void ldsm_x4(u32* r, u32 addr) {
    asm volatile("ldmatrix.sync.aligned.m8n8.x4.shared.b16 {%0,%1,%2,%3}, [%4];"
        : "=r"(r[0]), "=r"(r[1]), "=r"(r[2]), "=r"(r[3]) : "r"(addr));
}

__global__ void __launch_bounds__(512, 1)
dist_kernel(const float* __restrict__ x, const float* __restrict__ y,
            float* __restrict__ out) {
    extern __shared__ __align__(16) char smem[];
    u64* xsT = reinterpret_cast<u64*>(smem + XS_OFF);   // [NDD2][XTS] f32 packed
    u64* ysT = reinterpret_cast<u64*>(smem + YS_OFF);   // [NDD2][YTS] (-y) packed
    u32* xhi = reinterpret_cast<u32*>(smem + XHI_OFF);  // [BM][BTS] bf16-pair hi
    u32* xlo = reinterpret_cast<u32*>(smem + XLO_OFF);
    u32* yhi = reinterpret_cast<u32*>(smem + YHI_OFF);  // [BN][BTS] (+y)
    u32* ylo = reinterpret_cast<u32*>(smem + YLO_OFF);
    float* nsq = reinterpret_cast<float*>(smem + NSQ_OFF); // [192]: 128 x + 64 y
    float* nrn = reinterpret_cast<float*>(smem + NRN_OFF);
    float* dotm = reinterpret_cast<float*>(smem + XHI_OFF); // reuses xhi after loop

    const int R0 = blockIdx.x * BM;     // grid.x = 16
    const int C0 = blockIdx.y * BN;     // grid.y = 8
    const int t  = threadIdx.x;
    const int tx = t & 31;
    const int ty = t >> 5;

    // ---- stage x: f32 transposed + bf16 hi/lo row-major
    #pragma unroll
    for (int s = 0; s < 8; s++) {
        int idx  = t + 512 * s;         // 0..4095
        int row  = idx >> 5;            // 0..127
        int col4 = idx & 31;
        float4 v = *reinterpret_cast<const float4*>(
            x + (size_t)(R0 + row) * D_DIM + col4 * 4);
        xsT[(2 * col4) * XTS + row]     = pack2(v.x, v.y);
        xsT[(2 * col4 + 1) * XTS + row] = pack2(v.z, v.w);
        u32 h0 = bfpack(v.x, v.y);
        u32 h1 = bfpack(v.z, v.w);
        u32 l0 = bfpack(v.x - bflo_f(h0), v.y - bfhi_f(h0));
        u32 l1 = bfpack(v.z - bflo_f(h1), v.w - bfhi_f(h1));
        xhi[row * BTS + 2 * col4]     = h0;
        xhi[row * BTS + 2 * col4 + 1] = h1;
        xlo[row * BTS + 2 * col4]     = l0;
        xlo[row * BTS + 2 * col4 + 1] = l1;
    }
    // ---- stage y: negated f32 transposed + positive bf16 hi/lo
    #pragma unroll
    for (int s = 0; s < 4; s++) {
        int idx  = t + 512 * s;         // 0..2047
        int row  = idx >> 5;            // 0..63
        int col4 = idx & 31;
        float4 v = *reinterpret_cast<const float4*>(
            y + (size_t)(C0 + row) * D_DIM + col4 * 4);
        ysT[(2 * col4) * YTS + row]     = pack2(-v.x, -v.y);
        ysT[(2 * col4 + 1) * YTS + row] = pack2(-v.z, -v.w);
        u32 h0 = bfpack(v.x, v.y);
        u32 h1 = bfpack(v.z, v.w);
        u32 l0 = bfpack(v.x - bflo_f(h0), v.y - bfhi_f(h0));
        u32 l1 = bfpack(v.z - bflo_f(h1), v.w - bfhi_f(h1));
        yhi[row * BTS + 2 * col4]     = h0;
        yhi[row * BTS + 2 * col4 + 1] = h1;
        ylo[row * BTS + 2 * col4]     = l0;
        ylo[row * BTS + 2 * col4 + 1] = l1;
    }
    __syncthreads();

    // ---- fused norms: t<128 -> x row t; 128<=t<192 -> y row t-128
    if (t < 192) {
        const u64* base; int stride;
        if (t < 128) { base = xsT + t;         stride = XTS; }
        else         { base = ysT + (t - 128); stride = YTS; }
        u64 a = 0ULL;
        #pragma unroll 8
        for (int dd2 = 0; dd2 < NDD2; dd2++) {
            u64 v = base[dd2 * stride];
            a = ffma2(v, v, a);
        }
        float s = f2lo(a) + f2hi(a);
        nsq[t] = s;
        nrn[t] = rsqrtf(s);
    }
    __syncthreads();

    // ================= merged mainloop: MMA k-steps interleaved with L1 =====
    const int w    = ty;
    const int lane = tx;
    const int gid  = lane >> 2;     // 0..7
    const int tig  = lane & 3;      // 0..3
    const int m0   = (w >> 1) * 16; // 8 m-tiles of 16 rows
    const int nh   = (w & 1) * 32;  // n half

    // ldmatrix lane addresses
    const int arow = m0 + (lane & 15);
    const int acol = (lane >> 4) * 4;
    u32 xhi_sa = (u32)__cvta_generic_to_shared(xhi);
    u32 xlo_sa = (u32)__cvta_generic_to_shared(xlo);
    u32 yhi_sa = (u32)__cvta_generic_to_shared(yhi);
    u32 ylo_sa = (u32)__cvta_generic_to_shared(ylo);
    u32 aOff = (u32)(arow * BTS + acol) << 2;
    const int brow = (lane & 7) + ((lane >> 4) & 1) * 8;
    const int bcol = ((lane >> 3) & 1) * 4;
    u32 bOff0 = (u32)((nh + brow) * BTS + bcol) << 2;
    u32 bOff1 = (u32)((nh + 16 + brow) * BTS + bcol) << 2;

    float c[4][4];
    #pragma unroll
    for (int nt = 0; nt < 4; nt++)
        #pragma unroll
        for (int q = 0; q < 4; q++) c[nt][q] = 0.0f;

    const u64 ABSM = 0x7FFFFFFF7FFFFFFFULL;
    u64 acc1[8][2];
    #pragma unroll
    for (int i = 0; i < 8; i++) { acc1[i][0] = 0ULL; acc1[i][1] = 0ULL; }

    const u64*  px = xsT + ty;                                    // x rows ty+16i
    const ull2* py = reinterpret_cast<const ull2*>(ysT + 2 * tx); // y cols 2tx,2tx+1

    for (int g = 0; g < 8; g++) {
        // ---- one MMA k-step (tensor + LSU pipes) ----
        {
            u32 kb = (u32)(g * 8) << 2;   // byte advance (8 u32 per step)
            u32 ah[4], al[4], bh0[4], bh1[4], bl0[4], bl1[4];
            ldsm_x4(ah, xhi_sa + aOff + kb);
            ldsm_x4(al, xlo_sa + aOff + kb);
            ldsm_x4(bh0, yhi_sa + bOff0 + kb);
            ldsm_x4(bh1, yhi_sa + bOff1 + kb);
            ldsm_x4(bl0, ylo_sa + bOff0 + kb);
            ldsm_x4(bl1, ylo_sa + bOff1 + kb);

            mma_bf16(c[0], ah, bh0[0], bh0[1]);
            mma_bf16(c[0], ah, bl0[0], bl0[1]);
            mma_bf16(c[0], al, bh0[0], bh0[1]);
            mma_bf16(c[1], ah, bh0[2], bh0[3]);
            mma_bf16(c[1], ah, bl0[2], bl0[3]);
            mma_bf16(c[1], al, bh0[2], bh0[3]);
            mma_bf16(c[2], ah, bh1[0], bh1[1]);
            mma_bf16(c[2], ah, bl1[0], bl1[1]);
            mma_bf16(c[2], al, bh1[0], bh1[1]);
            mma_bf16(c[3], ah, bh1[2], bh1[3]);
            mma_bf16(c[3], ah, bl1[2], bl1[3]);
            mma_bf16(c[3], al, bh1[2], bh1[3]);
        }

        // ---- 8 dd2 of L1 (fma pipe) ----
        #pragma unroll
        for (int u = 0; u < 8; u++) {
            u64 xv[8];
            #pragma unroll
            for (int i = 0; i < 8; i++) xv[i] = px[16 * i];   // broadcast LDS.64
            ull2 yv = *py;                                    // LDS.128

            #pragma unroll
            for (int i = 0; i < 8; i++) {
                u64 e0 = fadd2(xv[i], yv.x);
                u64 e1 = fadd2(xv[i], yv.y);
                acc1[i][0] = fadd2(acc1[i][0], e0 & ABSM);
                acc1[i][1] = fadd2(acc1[i][1], e1 & ABSM);
            }

            px += XTS;
            py += YTS / 2;
        }
    }

    __syncthreads();   // all warps done reading bf16 tiles

    // store dot fragments into smem (overwrites xhi region)
    #pragma unroll
    for (int nt = 0; nt < 4; nt++) {
        #pragma unroll
        for (int qh = 0; qh < 2; qh++) {
            int lr = m0 + gid + qh * 8;
            int lc = nh + nt * 8 + 2 * tig;
            *reinterpret_cast<float2*>(&dotm[lr * DTS + lc]) =
                make_float2(c[nt][qh * 2], c[nt][qh * 2 + 1]);
        }
    }
    __syncthreads();

    // ---- single coalesced epilogue: all 3 fields, 3x STG.64 per row ----
    #pragma unroll
    for (int i = 0; i < 8; i++) {
        int lrow = ty + 16 * i;
        int gr = R0 + lrow;
        float xsq = nsq[lrow];
        float xrn = nrn[lrow];
        float2 dv = *reinterpret_cast<const float2*>(&dotm[lrow * DTS + 2 * tx]);
        float o[6];
        #pragma unroll
        for (int j = 0; j < 2; j++) {
            int lcol = 2 * tx + j;
            float dot = (j == 0) ? dv.x : dv.y;
            float s1 = f2lo(acc1[i][j]) + f2hi(acc1[i][j]);
            float s2 = fmaxf(xsq + nsq[128 + lcol] - 2.0f * dot, 0.0f);
            float p2 = sqrtf(s2);
            float cosv = dot * xrn * nrn[128 + lcol];
            o[3 * j + 0] = cosv;
            o[3 * j + 1] = s1;
            o[3 * j + 2] = p2;
        }
        size_t base = ((size_t)gr * C_TOTAL + C0 + 2 * tx) * 3;
        float2* dst = reinterpret_cast<float2*>(out + base);
        dst[0] = make_float2(o[0], o[1]);
        dst[1] = make_float2(o[2], o[3]);
        dst[2] = make_float2(o[4], o[5]);
    }
}

extern "C" void kernel_launch(void* const* d_in, const int* in_sizes, int n_in,
                              void* d_out, int out_size) {
    const float* x = (const float*)d_in[0];
    const float* y = (const float*)d_in[1];
    float* out = (float*)d_out;

    static int attr_done = 0;
    if (!attr_done) {
        cudaFuncSetAttribute(dist_kernel,
                             cudaFuncAttributeMaxDynamicSharedMemorySize, SMEM_BYTES);
        cudaFuncSetAttribute(dist_kernel,
                             cudaFuncAttributePreferredSharedMemoryCarveout, 100);
        attr_done = 1;
    }

    dim3 grid(R_TOTAL / BM, C_TOTAL / BN);   // 16 x 8 = 128 blocks, 1 CTA/SM, one wave
    dist_kernel<<<grid, 512, SMEM_BYTES>>>(x, y, out);
}